// round 14
// baseline (speedup 1.0000x reference)
#include <cuda_runtime.h>
#include <cuda_fp16.h>

// warp3D: out[b,c,z,y,x] = trilinear gather of I at (x+fx, y+fy, z+fz)
// B=2, C=2, D=160, H=192, W=224, fp32 in/out.
//
// Pass 1: pack I -> fp16 "half4" per voxel (8 B):
//   It[b,z,y,x] = h(c0[x]), h(c1[x]), h(c0[x+1]), h(c1[x+1])
// Pass 2: 4 x 8B gathers per voxel; 4 voxels per thread (y-quad).
// R14: main at __launch_bounds__(224,6) — 48 regs / 42 warps, continuing
//   the R10(32r/58w)=108 -> R11(71r/28w)=102 -> R12(56r/35w)=95.6 trend.
//   Pack reads back to __ldg (R13 showed __ldcs there cost ~2us).
//   Main keeps __ldcs on flow (streamed once) and __stcs on out
//   (write-once) to protect It's L2 residency.

#define Wd 224
#define Hd 192
#define Dd 160
#define Bd 2
#define HWd (Hd * Wd)            // 43008
#define DHWd (Dd * HWd)          // 6881280
#define VPT 4                    // voxels per thread (along y)

__device__ __forceinline__ unsigned int h2_to_u(__half2 h) {
    return *reinterpret_cast<unsigned int*>(&h);
}
__device__ __forceinline__ __half2 u_to_h2(unsigned int u) {
    return *reinterpret_cast<__half2*>(&u);
}

// 13.76M voxels * 8B = 110 MB scratch
__device__ uint2 g_It[(long)Bd * DHWd];

// Pack: thread = x-quad (4 voxels). Block (56,4) = 224 thr covers 4 y-rows.
__global__ __launch_bounds__(224) void pack_kernel(const float* __restrict__ I)
{
    const int q = threadIdx.x;                 // 0..55  (x quad = 4q..4q+3)
    const int y = blockIdx.x * 4 + threadIdx.y;
    const int z = blockIdx.y;
    const int b = blockIdx.z;

    const int x = 4 * q;
    const int s = z * HWd + y * Wd + x;        // 16B aligned
    const float* __restrict__ I0 = I + (long)b * 2 * DHWd;
    const float* __restrict__ I1 = I0 + DHWd;

    const float4 a = __ldg((const float4*)(I0 + s));   // c0[x..x+3]
    const float4 c = __ldg((const float4*)(I1 + s));   // c1[x..x+3]
    const int sn = s - x + min(x + 4, Wd - 1);          // x+4, edge-clamped
    const float n0 = __ldg(I0 + sn);
    const float n1 = __ldg(I1 + sn);

    const unsigned int e0 = h2_to_u(__floats2half2_rn(a.x, c.x));  // x
    const unsigned int e1 = h2_to_u(__floats2half2_rn(a.y, c.y));  // x+1
    const unsigned int e2 = h2_to_u(__floats2half2_rn(a.z, c.z));  // x+2
    const unsigned int e3 = h2_to_u(__floats2half2_rn(a.w, c.w));  // x+3
    const unsigned int e4 = h2_to_u(__floats2half2_rn(n0,  n1));   // x+4

    uint4* __restrict__ dst = reinterpret_cast<uint4*>(g_It + (long)b * DHWd + s);
    dst[0] = make_uint4(e0, e1, e1, e2);   // voxels x, x+1
    dst[1] = make_uint4(e2, e3, e3, e4);   // voxels x+2, x+3
}

// Gather: block 224 thr = one x-row; each thread does VPT voxels (y..y+3).
// minBlocks=6 -> regs capped ~48 -> 6 blocks/SM (42 warps).
__global__ __launch_bounds__(Wd, 6) void warp3d_kernel(
    const float* __restrict__ flow,
    float* __restrict__ out)
{
    const int x  = threadIdx.x;          // 0..223
    const int yb = blockIdx.x * VPT;     // 0..188 step 4
    const int z  = blockIdx.y;           // 0..159
    const int b  = blockIdx.z;           // 0..1

    const float* __restrict__ fb = flow + (long)b * 3 * DHWd;
    const uint2* __restrict__ Ic = g_It + (long)b * DHWd;
    float* __restrict__ ob = out + (long)b * 2 * DHWd;

    const int s0 = z * HWd + yb * Wd + x;

    // ---- Stage A: all flow loads in flight (12 LDG.32, evict-first) ----
    float fxv[VPT], fyv[VPT], fzv[VPT];
#pragma unroll
    for (int v = 0; v < VPT; ++v) {
        const int s = s0 + v * Wd;
        fxv[v] = __ldcs(fb + s);
        fyv[v] = __ldcs(fb + s + DHWd);
        fzv[v] = __ldcs(fb + s + 2L * DHWd);
    }

    // ---- Stage B: coords + gathers in flight (16 LDG.64) ----
    float w00[VPT], w10[VPT], w01[VPT], w11[VPT], dzv[VPT], ezv[VPT];
    uint2 A0[VPT], A1[VPT], B0[VPT], B1[VPT];
    bool  xeq[VPT];

#pragma unroll
    for (int v = 0; v < VPT; ++v) {
        const int y = yb + v;
        const float xf = fxv[v] + (float)x;
        const float yf = fyv[v] + (float)y;
        const float zf = fzv[v] + (float)z;

        int x0 = (int)floorf(xf);
        int y0 = (int)floorf(yf);
        int z0 = (int)floorf(zf);
        // upper corner from UNclamped lower+1, then clamp (matches ref)
        const int x1 = min(max(x0 + 1, 0), Wd - 1);
        const int y1 = min(max(y0 + 1, 0), Hd - 1);
        const int z1 = min(max(z0 + 1, 0), Dd - 1);
        x0 = min(max(x0, 0), Wd - 1);
        y0 = min(max(y0, 0), Hd - 1);
        z0 = min(max(z0, 0), Dd - 1);

        const float dx = (float)x1 - xf;
        const float dy = (float)y1 - yf;
        const float dz = (float)z1 - zf;
        const float ex = 1.0f - dx;
        const float ey = 1.0f - dy;

        w00[v] = dx * dy;
        w10[v] = dx * ey;
        w01[v] = ex * dy;
        w11[v] = ex * ey;
        dzv[v] = dz;
        ezv[v] = 1.0f - dz;
        xeq[v] = (x1 == x0);

        const int r00 = z0 * HWd + y0 * Wd + x0;
        const int r10 = z0 * HWd + y1 * Wd + x0;
        const int r01 = z1 * HWd + y0 * Wd + x0;
        const int r11 = z1 * HWd + y1 * Wd + x0;

        A0[v] = __ldg(Ic + r00);
        A1[v] = __ldg(Ic + r10);
        B0[v] = __ldg(Ic + r01);
        B1[v] = __ldg(Ic + r11);
    }

    // ---- Stage C: clamp-fix, convert, reduce, store (evict-first) ----
#pragma unroll
    for (int v = 0; v < VPT; ++v) {
        if (xeq[v]) {   // below-range x clamp: hi pair := lo pair
            A0[v].y = A0[v].x;
            A1[v].y = A1[v].x;
            B0[v].y = B0[v].x;
            B1[v].y = B1[v].x;
        }

        const float2 a0l = __half22float2(u_to_h2(A0[v].x));
        const float2 a0h = __half22float2(u_to_h2(A0[v].y));
        const float2 a1l = __half22float2(u_to_h2(A1[v].x));
        const float2 a1h = __half22float2(u_to_h2(A1[v].y));
        const float2 b0l = __half22float2(u_to_h2(B0[v].x));
        const float2 b0h = __half22float2(u_to_h2(B0[v].y));
        const float2 b1l = __half22float2(u_to_h2(B1[v].x));
        const float2 b1h = __half22float2(u_to_h2(B1[v].y));

        const float p0c0 = w00[v]*a0l.x + w10[v]*a1l.x + w01[v]*a0h.x + w11[v]*a1h.x;
        const float p0c1 = w00[v]*a0l.y + w10[v]*a1l.y + w01[v]*a0h.y + w11[v]*a1h.y;
        const float p1c0 = w00[v]*b0l.x + w10[v]*b1l.x + w01[v]*b0h.x + w11[v]*b1h.x;
        const float p1c1 = w00[v]*b0l.y + w10[v]*b1l.y + w01[v]*b0h.y + w11[v]*b1h.y;

        const int s = s0 + v * Wd;
        __stcs(ob + s,        dzv[v] * p0c0 + ezv[v] * p1c0);
        __stcs(ob + s + DHWd, dzv[v] * p0c1 + ezv[v] * p1c1);
    }
}

extern "C" void kernel_launch(void* const* d_in, const int* in_sizes, int n_in,
                              void* d_out, int out_size)
{
    const float* I    = (const float*)d_in[0];
    const float* flow = (const float*)d_in[1];
    float* out        = (float*)d_out;

    dim3 pblock(56, 4, 1);                  // 224 thr
    dim3 pgrid(Hd / 4, Dd, Bd);             // 48 x 160 x 2
    pack_kernel<<<pgrid, pblock>>>(I);

    dim3 block(Wd, 1, 1);                   // 224 thr
    dim3 grid(Hd / VPT, Dd, Bd);            // 48 x 160 x 2
    warp3d_kernel<<<grid, block>>>(flow, out);
}

// round 15
// speedup vs baseline: 1.0969x; 1.0969x over previous
#include <cuda_runtime.h>
#include <cuda_fp16.h>

// warp3D: out[b,c,z,y,x] = trilinear gather of I at (x+fx, y+fy, z+fz)
// B=2, C=2, D=160, H=192, W=224, fp32 in/out.
//
// Tuned configuration (R15 = best measured halves composed):
//  Pass 1 (R12 pack, 33.5us): I -> fp16 "half4" per voxel (8 B):
//    It[b,z,y,x] = h(c0[x]), h(c1[x]), h(c0[x+1]), h(c1[x+1])
//    x-quad per thread, plain __ldg reads (R13: __ldcs here costs ~2us).
//  Pass 2 (R13 main, 95.6us): 4 x LDG.64 gathers per voxel, 4 voxels per
//    thread (y-quad), __launch_bounds__(224,5) -> 56 regs / 35 warps
//    (measured optimum of the reg/occupancy sweep R10-R14);
//    __ldcs on flow (streamed once), __stcs on out (write-once) to keep
//    the 110 MB It array L2-resident for the gathers.

#define Wd 224
#define Hd 192
#define Dd 160
#define Bd 2
#define HWd (Hd * Wd)            // 43008
#define DHWd (Dd * HWd)          // 6881280
#define VPT 4                    // voxels per thread (along y)

__device__ __forceinline__ unsigned int h2_to_u(__half2 h) {
    return *reinterpret_cast<unsigned int*>(&h);
}
__device__ __forceinline__ __half2 u_to_h2(unsigned int u) {
    return *reinterpret_cast<__half2*>(&u);
}

// 13.76M voxels * 8B = 110 MB scratch
__device__ uint2 g_It[(long)Bd * DHWd];

// Pack: thread = x-quad (4 voxels). Block (56,4) = 224 thr covers 4 y-rows.
__global__ __launch_bounds__(224) void pack_kernel(const float* __restrict__ I)
{
    const int q = threadIdx.x;                 // 0..55  (x quad = 4q..4q+3)
    const int y = blockIdx.x * 4 + threadIdx.y;
    const int z = blockIdx.y;
    const int b = blockIdx.z;

    const int x = 4 * q;
    const int s = z * HWd + y * Wd + x;        // 16B aligned
    const float* __restrict__ I0 = I + (long)b * 2 * DHWd;
    const float* __restrict__ I1 = I0 + DHWd;

    const float4 a = __ldg((const float4*)(I0 + s));   // c0[x..x+3]
    const float4 c = __ldg((const float4*)(I1 + s));   // c1[x..x+3]
    const int sn = s - x + min(x + 4, Wd - 1);          // x+4, edge-clamped
    const float n0 = __ldg(I0 + sn);
    const float n1 = __ldg(I1 + sn);

    const unsigned int e0 = h2_to_u(__floats2half2_rn(a.x, c.x));  // x
    const unsigned int e1 = h2_to_u(__floats2half2_rn(a.y, c.y));  // x+1
    const unsigned int e2 = h2_to_u(__floats2half2_rn(a.z, c.z));  // x+2
    const unsigned int e3 = h2_to_u(__floats2half2_rn(a.w, c.w));  // x+3
    const unsigned int e4 = h2_to_u(__floats2half2_rn(n0,  n1));   // x+4

    uint4* __restrict__ dst = reinterpret_cast<uint4*>(g_It + (long)b * DHWd + s);
    dst[0] = make_uint4(e0, e1, e1, e2);   // voxels x, x+1
    dst[1] = make_uint4(e2, e3, e3, e4);   // voxels x+2, x+3
}

// Gather: block 224 thr = one x-row; each thread does VPT voxels (y..y+3).
// minBlocks=5 -> 56 regs, 5 blocks/SM = 35 warps (measured optimum).
__global__ __launch_bounds__(Wd, 5) void warp3d_kernel(
    const float* __restrict__ flow,
    float* __restrict__ out)
{
    const int x  = threadIdx.x;          // 0..223
    const int yb = blockIdx.x * VPT;     // 0..188 step 4
    const int z  = blockIdx.y;           // 0..159
    const int b  = blockIdx.z;           // 0..1

    const float* __restrict__ fb = flow + (long)b * 3 * DHWd;
    const uint2* __restrict__ Ic = g_It + (long)b * DHWd;
    float* __restrict__ ob = out + (long)b * 2 * DHWd;

    const int s0 = z * HWd + yb * Wd + x;

    // ---- Stage A: all flow loads in flight (12 LDG.32, evict-first) ----
    float fxv[VPT], fyv[VPT], fzv[VPT];
#pragma unroll
    for (int v = 0; v < VPT; ++v) {
        const int s = s0 + v * Wd;
        fxv[v] = __ldcs(fb + s);
        fyv[v] = __ldcs(fb + s + DHWd);
        fzv[v] = __ldcs(fb + s + 2L * DHWd);
    }

    // ---- Stage B: coords + all gathers in flight (16 LDG.64) ----
    float w00[VPT], w10[VPT], w01[VPT], w11[VPT], dzv[VPT], ezv[VPT];
    uint2 A0[VPT], A1[VPT], B0[VPT], B1[VPT];
    bool  xeq[VPT];

#pragma unroll
    for (int v = 0; v < VPT; ++v) {
        const int y = yb + v;
        const float xf = fxv[v] + (float)x;
        const float yf = fyv[v] + (float)y;
        const float zf = fzv[v] + (float)z;

        int x0 = (int)floorf(xf);
        int y0 = (int)floorf(yf);
        int z0 = (int)floorf(zf);
        // upper corner from UNclamped lower+1, then clamp (matches ref)
        const int x1 = min(max(x0 + 1, 0), Wd - 1);
        const int y1 = min(max(y0 + 1, 0), Hd - 1);
        const int z1 = min(max(z0 + 1, 0), Dd - 1);
        x0 = min(max(x0, 0), Wd - 1);
        y0 = min(max(y0, 0), Hd - 1);
        z0 = min(max(z0, 0), Dd - 1);

        const float dx = (float)x1 - xf;
        const float dy = (float)y1 - yf;
        const float dz = (float)z1 - zf;
        const float ex = 1.0f - dx;
        const float ey = 1.0f - dy;

        w00[v] = dx * dy;
        w10[v] = dx * ey;
        w01[v] = ex * dy;
        w11[v] = ex * ey;
        dzv[v] = dz;
        ezv[v] = 1.0f - dz;
        xeq[v] = (x1 == x0);

        const int r00 = z0 * HWd + y0 * Wd + x0;
        const int r10 = z0 * HWd + y1 * Wd + x0;
        const int r01 = z1 * HWd + y0 * Wd + x0;
        const int r11 = z1 * HWd + y1 * Wd + x0;

        A0[v] = __ldg(Ic + r00);
        A1[v] = __ldg(Ic + r10);
        B0[v] = __ldg(Ic + r01);
        B1[v] = __ldg(Ic + r11);
    }

    // ---- Stage C: clamp-fix, convert, reduce, store (evict-first) ----
#pragma unroll
    for (int v = 0; v < VPT; ++v) {
        if (xeq[v]) {   // below-range x clamp: hi pair := lo pair
            A0[v].y = A0[v].x;
            A1[v].y = A1[v].x;
            B0[v].y = B0[v].x;
            B1[v].y = B1[v].x;
        }

        const float2 a0l = __half22float2(u_to_h2(A0[v].x));
        const float2 a0h = __half22float2(u_to_h2(A0[v].y));
        const float2 a1l = __half22float2(u_to_h2(A1[v].x));
        const float2 a1h = __half22float2(u_to_h2(A1[v].y));
        const float2 b0l = __half22float2(u_to_h2(B0[v].x));
        const float2 b0h = __half22float2(u_to_h2(B0[v].y));
        const float2 b1l = __half22float2(u_to_h2(B1[v].x));
        const float2 b1h = __half22float2(u_to_h2(B1[v].y));

        const float p0c0 = w00[v]*a0l.x + w10[v]*a1l.x + w01[v]*a0h.x + w11[v]*a1h.x;
        const float p0c1 = w00[v]*a0l.y + w10[v]*a1l.y + w01[v]*a0h.y + w11[v]*a1h.y;
        const float p1c0 = w00[v]*b0l.x + w10[v]*b1l.x + w01[v]*b0h.x + w11[v]*b1h.x;
        const float p1c1 = w00[v]*b0l.y + w10[v]*b1l.y + w01[v]*b0h.y + w11[v]*b1h.y;

        const int s = s0 + v * Wd;
        __stcs(ob + s,        dzv[v] * p0c0 + ezv[v] * p1c0);
        __stcs(ob + s + DHWd, dzv[v] * p0c1 + ezv[v] * p1c1);
    }
}

extern "C" void kernel_launch(void* const* d_in, const int* in_sizes, int n_in,
                              void* d_out, int out_size)
{
    const float* I    = (const float*)d_in[0];
    const float* flow = (const float*)d_in[1];
    float* out        = (float*)d_out;

    dim3 pblock(56, 4, 1);                  // 224 thr
    dim3 pgrid(Hd / 4, Dd, Bd);             // 48 x 160 x 2
    pack_kernel<<<pgrid, pblock>>>(I);

    dim3 block(Wd, 1, 1);                   // 224 thr
    dim3 grid(Hd / VPT, Dd, Bd);            // 48 x 160 x 2
    warp3d_kernel<<<grid, block>>>(flow, out);
}

// round 16
// speedup vs baseline: 1.1572x; 1.0550x over previous
#include <cuda_runtime.h>
#include <cuda_fp16.h>

// warp3D: out[b,c,z,y,x] = trilinear gather of I at (x+fx, y+fy, z+fz)
// B=2, C=2, D=160, H=192, W=224, fp32 in/out.
//
// R16 layout: It[b,z,y,x] = half2(c0, c1)  -- 4 B/voxel, 55 MB total
//   (fully L2-resident; pack traffic drops 220->165 MB).
// Main: 8 x LDG.32 gathers per voxel (x0 and x1 fetched exactly -> no
//   clamp fixup), 4 voxels per thread (y-quad), __launch_bounds__(224,5)
//   (measured optimum: 56 regs / 35 warps), __ldcs flow / __stcs out.

#define Wd 224
#define Hd 192
#define Dd 160
#define Bd 2
#define HWd (Hd * Wd)            // 43008
#define DHWd (Dd * HWd)          // 6881280
#define VPT 4                    // voxels per thread (along y)

__device__ __forceinline__ unsigned int h2_to_u(__half2 h) {
    return *reinterpret_cast<unsigned int*>(&h);
}
__device__ __forceinline__ __half2 u_to_h2(unsigned int u) {
    return *reinterpret_cast<__half2*>(&u);
}

// 13.76M voxels * 4B = 55 MB scratch (L2-resident)
__device__ unsigned int g_It[(long)Bd * DHWd];

// Pack: thread = x-quad (4 voxels): 2 x LDG.128 -> 1 x STG.128.
__global__ __launch_bounds__(224) void pack_kernel(const float* __restrict__ I)
{
    const int q = threadIdx.x;                 // 0..55  (x quad = 4q..4q+3)
    const int y = blockIdx.x * 4 + threadIdx.y;
    const int z = blockIdx.y;
    const int b = blockIdx.z;

    const int x = 4 * q;
    const int s = z * HWd + y * Wd + x;        // 16B aligned
    const float* __restrict__ I0 = I + (long)b * 2 * DHWd;
    const float* __restrict__ I1 = I0 + DHWd;

    const float4 a = __ldg((const float4*)(I0 + s));   // c0[x..x+3]
    const float4 c = __ldg((const float4*)(I1 + s));   // c1[x..x+3]

    uint4 v;
    v.x = h2_to_u(__floats2half2_rn(a.x, c.x));
    v.y = h2_to_u(__floats2half2_rn(a.y, c.y));
    v.z = h2_to_u(__floats2half2_rn(a.z, c.z));
    v.w = h2_to_u(__floats2half2_rn(a.w, c.w));
    *reinterpret_cast<uint4*>(g_It + (long)b * DHWd + s) = v;
}

// Gather: block 224 thr = one x-row; each thread does VPT voxels (y..y+3).
__global__ __launch_bounds__(Wd, 5) void warp3d_kernel(
    const float* __restrict__ flow,
    float* __restrict__ out)
{
    const int x  = threadIdx.x;          // 0..223
    const int yb = blockIdx.x * VPT;     // 0..188 step 4
    const int z  = blockIdx.y;           // 0..159
    const int b  = blockIdx.z;           // 0..1

    const float* __restrict__ fb = flow + (long)b * 3 * DHWd;
    const unsigned int* __restrict__ Ic = g_It + (long)b * DHWd;
    float* __restrict__ ob = out + (long)b * 2 * DHWd;

    const int s0 = z * HWd + yb * Wd + x;

    // ---- Stage A: all flow loads in flight (12 LDG.32, evict-first) ----
    float fxv[VPT], fyv[VPT], fzv[VPT];
#pragma unroll
    for (int v = 0; v < VPT; ++v) {
        const int s = s0 + v * Wd;
        fxv[v] = __ldcs(fb + s);
        fyv[v] = __ldcs(fb + s + DHWd);
        fzv[v] = __ldcs(fb + s + 2L * DHWd);
    }

    // ---- Stage B: coords + all gathers in flight (32 LDG.32) ----
    float w00[VPT], w10[VPT], w01[VPT], w11[VPT], dzv[VPT], ezv[VPT];
    unsigned int a00[VPT], a01[VPT], a10[VPT], a11[VPT];
    unsigned int c00[VPT], c01[VPT], c10[VPT], c11[VPT];

#pragma unroll
    for (int v = 0; v < VPT; ++v) {
        const int y = yb + v;
        const float xf = fxv[v] + (float)x;
        const float yf = fyv[v] + (float)y;
        const float zf = fzv[v] + (float)z;

        int x0 = (int)floorf(xf);
        int y0 = (int)floorf(yf);
        int z0 = (int)floorf(zf);
        // upper corner from UNclamped lower+1, then clamp (matches ref)
        const int x1 = min(max(x0 + 1, 0), Wd - 1);
        const int y1 = min(max(y0 + 1, 0), Hd - 1);
        const int z1 = min(max(z0 + 1, 0), Dd - 1);
        x0 = min(max(x0, 0), Wd - 1);
        y0 = min(max(y0, 0), Hd - 1);
        z0 = min(max(z0, 0), Dd - 1);

        const float dx = (float)x1 - xf;
        const float dy = (float)y1 - yf;
        const float dz = (float)z1 - zf;
        const float ex = 1.0f - dx;
        const float ey = 1.0f - dy;

        w00[v] = dx * dy;    // (y0, x0)
        w01[v] = ex * dy;    // (y0, x1)
        w10[v] = dx * ey;    // (y1, x0)
        w11[v] = ex * ey;    // (y1, x1)
        dzv[v] = dz;
        ezv[v] = 1.0f - dz;

        const int r00 = z0 * HWd + y0 * Wd;
        const int r10 = z0 * HWd + y1 * Wd;
        const int r01 = z1 * HWd + y0 * Wd;
        const int r11 = z1 * HWd + y1 * Wd;

        a00[v] = __ldg(Ic + r00 + x0);
        a01[v] = __ldg(Ic + r00 + x1);
        a10[v] = __ldg(Ic + r10 + x0);
        a11[v] = __ldg(Ic + r10 + x1);
        c00[v] = __ldg(Ic + r01 + x0);
        c01[v] = __ldg(Ic + r01 + x1);
        c10[v] = __ldg(Ic + r11 + x0);
        c11[v] = __ldg(Ic + r11 + x1);
    }

    // ---- Stage C: convert, reduce, store (evict-first) ----
#pragma unroll
    for (int v = 0; v < VPT; ++v) {
        const float2 f00 = __half22float2(u_to_h2(a00[v]));
        const float2 f01 = __half22float2(u_to_h2(a01[v]));
        const float2 f10 = __half22float2(u_to_h2(a10[v]));
        const float2 f11 = __half22float2(u_to_h2(a11[v]));
        const float2 g00 = __half22float2(u_to_h2(c00[v]));
        const float2 g01 = __half22float2(u_to_h2(c01[v]));
        const float2 g10 = __half22float2(u_to_h2(c10[v]));
        const float2 g11 = __half22float2(u_to_h2(c11[v]));

        const float p0c0 = w00[v]*f00.x + w01[v]*f01.x + w10[v]*f10.x + w11[v]*f11.x;
        const float p0c1 = w00[v]*f00.y + w01[v]*f01.y + w10[v]*f10.y + w11[v]*f11.y;
        const float p1c0 = w00[v]*g00.x + w01[v]*g01.x + w10[v]*g10.x + w11[v]*g11.x;
        const float p1c1 = w00[v]*g00.y + w01[v]*g01.y + w10[v]*g10.y + w11[v]*g11.y;

        const int s = s0 + v * Wd;
        __stcs(ob + s,        dzv[v] * p0c0 + ezv[v] * p1c0);
        __stcs(ob + s + DHWd, dzv[v] * p0c1 + ezv[v] * p1c1);
    }
}

extern "C" void kernel_launch(void* const* d_in, const int* in_sizes, int n_in,
                              void* d_out, int out_size)
{
    const float* I    = (const float*)d_in[0];
    const float* flow = (const float*)d_in[1];
    float* out        = (float*)d_out;

    dim3 pblock(56, 4, 1);                  // 224 thr
    dim3 pgrid(Hd / 4, Dd, Bd);             // 48 x 160 x 2
    pack_kernel<<<pgrid, pblock>>>(I);

    dim3 block(Wd, 1, 1);                   // 224 thr
    dim3 grid(Hd / VPT, Dd, Bd);            // 48 x 160 x 2
    warp3d_kernel<<<grid, block>>>(flow, out);
}